// round 1
// baseline (speedup 1.0000x reference)
#include <cuda_runtime.h>

#define CC 192
#define HW_ 9216
#define PSTRIDE 59   // 33 softplus(mat) + 13 bias + 13 tanh(factor)

__device__ float d_param[CC * PSTRIDE];

__device__ __forceinline__ float fast_tanh(float x) {
    float y;
    asm("tanh.approx.f32 %0, %1;" : "=f"(y) : "f"(x));
    return y;
}

__device__ __forceinline__ float fast_sigmoid(float x) {
    float e = __expf(-x);
    return __fdividef(1.0f, 1.0f + e);
}

// -------------------------------------------------------------------------
// Per-(channel,unit) parameter preprocessing: softplus on matrices, tanh on
// factors, biases copied. 192*59 = 11328 slots; trivial cost, amortizes all
// parameter transcendentals out of the hot kernel.
// -------------------------------------------------------------------------
__global__ void eb_prep(
    const float* __restrict__ m0, const float* __restrict__ m1,
    const float* __restrict__ m2, const float* __restrict__ m3,
    const float* __restrict__ m4,
    const float* __restrict__ b0, const float* __restrict__ b1,
    const float* __restrict__ b2, const float* __restrict__ b3,
    const float* __restrict__ b4,
    const float* __restrict__ f0, const float* __restrict__ f1,
    const float* __restrict__ f2, const float* __restrict__ f3,
    const float* __restrict__ f4)
{
    int idx = blockIdx.x * blockDim.x + threadIdx.x;
    if (idx >= CC * PSTRIDE) return;
    int c = idx / PSTRIDE, s = idx % PSTRIDE;
    float val;
    if (s < 33) {
        const float* ms[5] = {m0, m1, m2, m3, m4};
        const int off[5] = {0, 3, 12, 21, 30};
        const int sz[5]  = {3, 9, 9, 9, 3};
        int l = (s < 3) ? 0 : (s < 12) ? 1 : (s < 21) ? 2 : (s < 30) ? 3 : 4;
        float x = ms[l][c * sz[l] + (s - off[l])];
        val = (x > 15.0f) ? x : log1pf(expf(x));   // softplus
    } else if (s < 46) {
        int u = s - 33;
        const float* bs[5] = {b0, b1, b2, b3, b4};
        const int off[5] = {0, 3, 6, 9, 12};
        const int sz[5]  = {3, 3, 3, 3, 1};
        int l = (u < 3) ? 0 : (u < 6) ? 1 : (u < 9) ? 2 : (u < 12) ? 3 : 4;
        val = bs[l][c * sz[l] + (u - off[l])];
    } else {
        int u = s - 46;
        const float* fs[5] = {f0, f1, f2, f3, f4};
        const int off[5] = {0, 3, 6, 9, 12};
        const int sz[5]  = {3, 3, 3, 3, 1};
        int l = (u < 3) ? 0 : (u < 6) ? 1 : (u < 9) ? 2 : (u < 12) ? 3 : 4;
        val = tanhf(fs[l][c * sz[l] + (u - off[l])]);
    }
    d_param[idx] = val;
}

// -------------------------------------------------------------------------
// logits_cumulative: 1 -> 3 -> 3 -> 3 -> 3 -> 1 tiny MLP, fully unrolled.
// G=false: gate factors are all zero (tanh(f)==0 makes the gate an exact
// no-op for finite activations) -> zero tanh on the hot path.
// -------------------------------------------------------------------------
template <bool G>
__device__ __forceinline__ float logits(const float* sp, const float* bb,
                                        const float* tf, float t)
{
    float h0 = fmaf(sp[0], t, bb[0]);
    float h1 = fmaf(sp[1], t, bb[1]);
    float h2 = fmaf(sp[2], t, bb[2]);
    if (G) {
        h0 += tf[0] * fast_tanh(h0);
        h1 += tf[1] * fast_tanh(h1);
        h2 += tf[2] * fast_tanh(h2);
    }
#pragma unroll
    for (int l = 1; l < 4; l++) {
        const float* M = sp + 3 + (l - 1) * 9;
        const float* B = bb + 3 * l;
        const float* T = tf + 3 * l;
        float g0 = fmaf(M[0], h0, fmaf(M[1], h1, fmaf(M[2], h2, B[0])));
        float g1 = fmaf(M[3], h0, fmaf(M[4], h1, fmaf(M[5], h2, B[1])));
        float g2 = fmaf(M[6], h0, fmaf(M[7], h1, fmaf(M[8], h2, B[2])));
        if (G) {
            g0 += T[0] * fast_tanh(g0);
            g1 += T[1] * fast_tanh(g1);
            g2 += T[2] * fast_tanh(g2);
        }
        h0 = g0; h1 = g1; h2 = g2;
    }
    float o = fmaf(sp[30], h0, fmaf(sp[31], h1, fmaf(sp[32], h2, bb[12])));
    if (G) o += tf[12] * fast_tanh(o);
    return o;
}

template <bool G>
__device__ __forceinline__ float likelihood_of(const float* sp, const float* bb,
                                               const float* tf, float v)
{
    float L = logits<G>(sp, bb, tf, v - 0.5f);
    float U = logits<G>(sp, bb, tf, v + 0.5f);
    float su = L + U;
    float s = (su > 0.0f) ? -1.0f : ((su < 0.0f) ? 1.0f : 0.0f);  // -sign(L+U)
    float lk = fabsf(fast_sigmoid(s * U) - fast_sigmoid(s * L));
    return fmaxf(lk, 1e-9f);
}

// -------------------------------------------------------------------------
// Hot kernel: 256 threads x 4 elements = 1024 elements per block; 1024
// divides H*W=9216 so every block sits in one channel slab -> one shared
// parameter fetch, params promoted to registers (each mat elem reused 8x).
// -------------------------------------------------------------------------
__global__ void __launch_bounds__(256) eb_main(
    const float4* __restrict__ x4, const float4* __restrict__ n4,
    float* __restrict__ out, int n4tot)
{
    __shared__ float P[PSTRIDE];
    int c = (int)((blockIdx.x * 1024u) / HW_) % CC;
    if (threadIdx.x < PSTRIDE) P[threadIdx.x] = d_param[c * PSTRIDE + threadIdx.x];
    __syncthreads();

    float sp[33], bb[13], tf[13];
#pragma unroll
    for (int i = 0; i < 33; i++) sp[i] = P[i];
#pragma unroll
    for (int i = 0; i < 13; i++) bb[i] = P[33 + i];
#pragma unroll
    for (int i = 0; i < 13; i++) tf[i] = P[46 + i];

    bool gated = false;
#pragma unroll
    for (int i = 0; i < 13; i++) gated = gated || (tf[i] != 0.0f);

    int i4 = blockIdx.x * 256 + threadIdx.x;
    float4 xv = x4[i4];
    float4 nv = n4[i4];
    float4 v = make_float4(xv.x + nv.x, xv.y + nv.y, xv.z + nv.z, xv.w + nv.w);

    float4* o4 = (float4*)out;
    o4[i4] = v;  // outputs = v

    float4 lk;
    if (!gated) {
        lk.x = likelihood_of<false>(sp, bb, tf, v.x);
        lk.y = likelihood_of<false>(sp, bb, tf, v.y);
        lk.z = likelihood_of<false>(sp, bb, tf, v.z);
        lk.w = likelihood_of<false>(sp, bb, tf, v.w);
    } else {
        lk.x = likelihood_of<true>(sp, bb, tf, v.x);
        lk.y = likelihood_of<true>(sp, bb, tf, v.y);
        lk.z = likelihood_of<true>(sp, bb, tf, v.z);
        lk.w = likelihood_of<true>(sp, bb, tf, v.w);
    }
    o4[n4tot + i4] = lk;  // likelihood
}

extern "C" void kernel_launch(void* const* d_in, const int* in_sizes, int n_in,
                              void* d_out, int out_size)
{
    const float* X  = (const float*)d_in[0];
    const float* NZ = (const float*)d_in[1];

    const float *m[5], *b[5], *f[5];
    // Disambiguate metadata ordering at runtime:
    //   signature order: inputs, noise, m0..m4, b0..b4, f0..f4  -> in_sizes[3]=1728 (m1)
    //   dict order:      inputs, noise, m0,b0,f0, m1,b1,f1, ... -> in_sizes[3]=576  (b0)
    if (in_sizes[3] == 3 * in_sizes[2]) {
        for (int i = 0; i < 5; i++) {
            m[i] = (const float*)d_in[2 + i];
            b[i] = (const float*)d_in[7 + i];
            f[i] = (const float*)d_in[12 + i];
        }
    } else {
        for (int i = 0; i < 5; i++) {
            m[i] = (const float*)d_in[2 + 3 * i];
            b[i] = (const float*)d_in[3 + 3 * i];
            f[i] = (const float*)d_in[4 + 3 * i];
        }
    }

    int N = in_sizes[0];  // B*C*H*W = 28,311,552

    eb_prep<<<(CC * PSTRIDE + 255) / 256, 256>>>(
        m[0], m[1], m[2], m[3], m[4],
        b[0], b[1], b[2], b[3], b[4],
        f[0], f[1], f[2], f[3], f[4]);

    int blocks = N / 1024;  // 256 threads * 4 elems
    eb_main<<<blocks, 256>>>((const float4*)X, (const float4*)NZ,
                             (float*)d_out, N / 4);
}

// round 5
// speedup vs baseline: 1.4595x; 1.4595x over previous
#include <cuda_runtime.h>

#define CC 192
#define HW_ 9216
#define PSTRIDE 59   // 33 softplus(mat) + 13 bias + 13 tanh(factor)

__device__ float  d_param[CC * PSTRIDE];
__device__ float4 d_affine[CC];   // {a, b - 0.5a, gated_flag, b}

__device__ __forceinline__ float fast_sigmoid(float x) {
    float e = __expf(-x);
    return __fdividef(1.0f, 1.0f + e);
}

__device__ __forceinline__ float softplus_f(float x) {
    return (x > 15.0f) ? x : log1pf(expf(x));
}

// -------------------------------------------------------------------------
// Prep: one thread per channel. Applies softplus to matrices / tanh to
// factors, stores the full transformed parameter block (for the gated
// fallback), and composes the network's affine collapse
//   logits(t) = a*t + b   (exact when all tanh gates are zero)
// -------------------------------------------------------------------------
__global__ void eb_prep(
    const float* __restrict__ m0, const float* __restrict__ m1,
    const float* __restrict__ m2, const float* __restrict__ m3,
    const float* __restrict__ m4,
    const float* __restrict__ b0, const float* __restrict__ b1,
    const float* __restrict__ b2, const float* __restrict__ b3,
    const float* __restrict__ b4,
    const float* __restrict__ f0, const float* __restrict__ f1,
    const float* __restrict__ f2, const float* __restrict__ f3,
    const float* __restrict__ f4)
{
    int c = blockIdx.x * blockDim.x + threadIdx.x;
    if (c >= CC) return;

    float sp[33], bb[13], tf[13];
#pragma unroll
    for (int i = 0; i < 3; i++) sp[i]      = softplus_f(m0[c * 3 + i]);
#pragma unroll
    for (int i = 0; i < 9; i++) sp[3 + i]  = softplus_f(m1[c * 9 + i]);
#pragma unroll
    for (int i = 0; i < 9; i++) sp[12 + i] = softplus_f(m2[c * 9 + i]);
#pragma unroll
    for (int i = 0; i < 9; i++) sp[21 + i] = softplus_f(m3[c * 9 + i]);
#pragma unroll
    for (int i = 0; i < 3; i++) sp[30 + i] = softplus_f(m4[c * 3 + i]);

#pragma unroll
    for (int i = 0; i < 3; i++) { bb[i] = b0[c*3+i]; bb[3+i] = b1[c*3+i];
                                  bb[6+i] = b2[c*3+i]; bb[9+i] = b3[c*3+i]; }
    bb[12] = b4[c];
#pragma unroll
    for (int i = 0; i < 3; i++) { tf[i] = tanhf(f0[c*3+i]); tf[3+i] = tanhf(f1[c*3+i]);
                                  tf[6+i] = tanhf(f2[c*3+i]); tf[9+i] = tanhf(f3[c*3+i]); }
    tf[12] = tanhf(f4[c]);

    float* P = d_param + c * PSTRIDE;
#pragma unroll
    for (int i = 0; i < 33; i++) P[i] = sp[i];
#pragma unroll
    for (int i = 0; i < 13; i++) P[33 + i] = bb[i];
#pragma unroll
    for (int i = 0; i < 13; i++) P[46 + i] = tf[i];

    bool gated = false;
#pragma unroll
    for (int i = 0; i < 13; i++) gated = gated || (tf[i] != 0.0f);

    // Affine composition: a_vec <- M*a_vec ; v_vec <- M*v_vec + b
    float a0 = sp[0], a1 = sp[1], a2 = sp[2];
    float v0 = bb[0], v1 = bb[1], v2 = bb[2];
#pragma unroll
    for (int l = 1; l < 4; l++) {
        const float* M = sp + 3 + (l - 1) * 9;
        const float* B = bb + 3 * l;
        float na0 = M[0]*a0 + M[1]*a1 + M[2]*a2;
        float na1 = M[3]*a0 + M[4]*a1 + M[5]*a2;
        float na2 = M[6]*a0 + M[7]*a1 + M[8]*a2;
        float nv0 = M[0]*v0 + M[1]*v1 + M[2]*v2 + B[0];
        float nv1 = M[3]*v0 + M[4]*v1 + M[5]*v2 + B[1];
        float nv2 = M[6]*v0 + M[7]*v1 + M[8]*v2 + B[2];
        a0 = na0; a1 = na1; a2 = na2;
        v0 = nv0; v1 = nv1; v2 = nv2;
    }
    float a_s = sp[30]*a0 + sp[31]*a1 + sp[32]*a2;
    float b_s = sp[30]*v0 + sp[31]*v1 + sp[32]*v2 + bb[12];

    d_affine[c] = make_float4(a_s, b_s - 0.5f * a_s, gated ? 1.0f : 0.0f, b_s);
}

// -------------------------------------------------------------------------
// Generic slow logits (gated fallback only). Loop-based, reads params from
// global each use -> tiny register footprint so it never taxes the fast path.
// -------------------------------------------------------------------------
__device__ __noinline__ float logits_slow(const float* __restrict__ P, float t)
{
    float h[3];
#pragma unroll 1
    for (int i = 0; i < 3; i++) {
        float g = fmaf(P[i], t, P[33 + i]);
        h[i] = g + P[46 + i] * tanhf(g);
    }
#pragma unroll 1
    for (int l = 1; l < 4; l++) {
        const float* M = P + 3 + (l - 1) * 9;
        float g[3];
#pragma unroll 1
        for (int r = 0; r < 3; r++) {
            float s = P[33 + 3 * l + r];
#pragma unroll 1
            for (int k = 0; k < 3; k++) s = fmaf(M[3 * r + k], h[k], s);
            g[r] = s + P[46 + 3 * l + r] * tanhf(s);
        }
        h[0] = g[0]; h[1] = g[1]; h[2] = g[2];
    }
    float o = P[33 + 12];
#pragma unroll 1
    for (int k = 0; k < 3; k++) o = fmaf(P[30 + k], h[k], o);
    return o + P[46 + 12] * tanhf(o);
}

__device__ __forceinline__ float lk_from_LU(float L, float U)
{
    float su = L + U;
    float s = (su > 0.0f) ? -1.0f : ((su < 0.0f) ? 1.0f : 0.0f);  // -sign(L+U)
    float lk = fabsf(fast_sigmoid(s * U) - fast_sigmoid(s * L));
    return fmaxf(lk, 1e-9f);
}

// -------------------------------------------------------------------------
// Hot kernel: pure streaming. 256 thr x 4 elems = 1024/block; 1024 | 9216
// so each block is channel-uniform. Fast path: L = fma(a,v,bm), U = L + a.
// -------------------------------------------------------------------------
__global__ void __launch_bounds__(256, 6) eb_main(
    const float4* __restrict__ x4, const float4* __restrict__ n4,
    float* __restrict__ out, int n4tot)
{
    int c = (int)((blockIdx.x * 1024u) / HW_) % CC;
    float4 A = d_affine[c];

    int i4 = blockIdx.x * 256 + threadIdx.x;
    float4 xv = __ldcs(x4 + i4);
    float4 nv = __ldcs(n4 + i4);
    float4 v = make_float4(xv.x + nv.x, xv.y + nv.y, xv.z + nv.z, xv.w + nv.w);

    float4* o4 = (float4*)out;
    __stcs(o4 + i4, v);  // outputs = v

    float4 lk;
    if (A.z == 0.0f) {
        float a = A.x, bm = A.y;
        float Lx = fmaf(a, v.x, bm), Ly = fmaf(a, v.y, bm);
        float Lz = fmaf(a, v.z, bm), Lw = fmaf(a, v.w, bm);
        lk.x = lk_from_LU(Lx, Lx + a);
        lk.y = lk_from_LU(Ly, Ly + a);
        lk.z = lk_from_LU(Lz, Lz + a);
        lk.w = lk_from_LU(Lw, Lw + a);
    } else {
        const float* P = d_param + c * PSTRIDE;
        lk.x = lk_from_LU(logits_slow(P, v.x - 0.5f), logits_slow(P, v.x + 0.5f));
        lk.y = lk_from_LU(logits_slow(P, v.y - 0.5f), logits_slow(P, v.y + 0.5f));
        lk.z = lk_from_LU(logits_slow(P, v.z - 0.5f), logits_slow(P, v.z + 0.5f));
        lk.w = lk_from_LU(logits_slow(P, v.w - 0.5f), logits_slow(P, v.w + 0.5f));
    }
    __stcs(o4 + n4tot + i4, lk);  // likelihood
}

extern "C" void kernel_launch(void* const* d_in, const int* in_sizes, int n_in,
                              void* d_out, int out_size)
{
    const float* X  = (const float*)d_in[0];
    const float* NZ = (const float*)d_in[1];

    const float *m[5], *b[5], *f[5];
    if (in_sizes[3] == 3 * in_sizes[2]) {      // signature order
        for (int i = 0; i < 5; i++) {
            m[i] = (const float*)d_in[2 + i];
            b[i] = (const float*)d_in[7 + i];
            f[i] = (const float*)d_in[12 + i];
        }
    } else {                                   // dict order m,b,f interleaved
        for (int i = 0; i < 5; i++) {
            m[i] = (const float*)d_in[2 + 3 * i];
            b[i] = (const float*)d_in[3 + 3 * i];
            f[i] = (const float*)d_in[4 + 3 * i];
        }
    }

    int N = in_sizes[0];  // B*C*H*W = 28,311,552

    eb_prep<<<1, CC>>>(
        m[0], m[1], m[2], m[3], m[4],
        b[0], b[1], b[2], b[3], b[4],
        f[0], f[1], f[2], f[3], f[4]);

    int blocks = N / 1024;  // 256 threads * 4 elems
    eb_main<<<blocks, 256>>>((const float4*)X, (const float4*)NZ,
                             (float*)d_out, N / 4);
}

// round 6
// speedup vs baseline: 1.5874x; 1.0876x over previous
#include <cuda_runtime.h>

#define CC 192
#define HW_ 9216
#define PSTRIDE 59   // 33 softplus(mat) + 13 bias + 13 tanh(factor)

__device__ float  d_param[CC * PSTRIDE];
__device__ float4 d_affine[CC];   // {a, b - 0.5a, gated_flag, b}

__device__ __forceinline__ float fast_sigmoid(float x) {
    float e = __expf(-x);
    return __fdividef(1.0f, 1.0f + e);
}

__device__ __forceinline__ float fast_tanh(float x) {
    float y;
    asm("tanh.approx.f32 %0, %1;" : "=f"(y) : "f"(x));
    return y;
}

__device__ __forceinline__ float softplus_fast(float x) {
    // |rel err| ~1e-6; exact passthrough for large x
    return (x > 15.0f) ? x : __logf(1.0f + __expf(x));
}

// -------------------------------------------------------------------------
// Prep: one WARP per channel (24 blocks x 256 thr = 8 warps/block). The 59
// parameter slots are spread across lanes (2 slots/lane max), transformed
// with fast intrinsics, staged to shared, then lane 0 composes the affine
// collapse  logits(t) = a*t + b  (exact when all tanh gates are zero).
// -------------------------------------------------------------------------
__global__ void __launch_bounds__(256) eb_prep(
    const float* __restrict__ m0, const float* __restrict__ m1,
    const float* __restrict__ m2, const float* __restrict__ m3,
    const float* __restrict__ m4,
    const float* __restrict__ b0, const float* __restrict__ b1,
    const float* __restrict__ b2, const float* __restrict__ b3,
    const float* __restrict__ b4,
    const float* __restrict__ f0, const float* __restrict__ f1,
    const float* __restrict__ f2, const float* __restrict__ f3,
    const float* __restrict__ f4)
{
    __shared__ float S[8][PSTRIDE];
    int warp = threadIdx.x >> 5;
    int lane = threadIdx.x & 31;
    int c = blockIdx.x * 8 + warp;
    if (c >= CC) return;

    const float* ms[5] = {m0, m1, m2, m3, m4};
    const float* bs[5] = {b0, b1, b2, b3, b4};
    const float* fs[5] = {f0, f1, f2, f3, f4};
    const int moff[5] = {0, 3, 12, 21, 30};
    const int msz[5]  = {3, 9, 9, 9, 3};
    const int uoff[5] = {0, 3, 6, 9, 12};
    const int usz[5]  = {3, 3, 3, 3, 1};

#pragma unroll
    for (int pass = 0; pass < 2; pass++) {
        int s = lane + pass * 32;
        if (s < PSTRIDE) {
            float val;
            if (s < 33) {
                int l = (s < 3) ? 0 : (s < 12) ? 1 : (s < 21) ? 2 : (s < 30) ? 3 : 4;
                val = softplus_fast(ms[l][c * msz[l] + (s - moff[l])]);
            } else if (s < 46) {
                int u = s - 33;
                int l = (u < 3) ? 0 : (u < 6) ? 1 : (u < 9) ? 2 : (u < 12) ? 3 : 4;
                val = bs[l][c * usz[l] + (u - uoff[l])];
            } else {
                int u = s - 46;
                int l = (u < 3) ? 0 : (u < 6) ? 1 : (u < 9) ? 2 : (u < 12) ? 3 : 4;
                val = fast_tanh(fs[l][c * usz[l] + (u - uoff[l])]);
            }
            d_param[c * PSTRIDE + s] = val;
            S[warp][s] = val;
        }
    }
    __syncwarp();

    if (lane == 0) {
        const float* sp = S[warp];
        const float* bb = S[warp] + 33;
        const float* tf = S[warp] + 46;

        bool gated = false;
#pragma unroll
        for (int i = 0; i < 13; i++) gated = gated || (tf[i] != 0.0f);

        float a0 = sp[0], a1 = sp[1], a2 = sp[2];
        float v0 = bb[0], v1 = bb[1], v2 = bb[2];
#pragma unroll
        for (int l = 1; l < 4; l++) {
            const float* M = sp + 3 + (l - 1) * 9;
            const float* B = bb + 3 * l;
            float na0 = M[0]*a0 + M[1]*a1 + M[2]*a2;
            float na1 = M[3]*a0 + M[4]*a1 + M[5]*a2;
            float na2 = M[6]*a0 + M[7]*a1 + M[8]*a2;
            float nv0 = M[0]*v0 + M[1]*v1 + M[2]*v2 + B[0];
            float nv1 = M[3]*v0 + M[4]*v1 + M[5]*v2 + B[1];
            float nv2 = M[6]*v0 + M[7]*v1 + M[8]*v2 + B[2];
            a0 = na0; a1 = na1; a2 = na2;
            v0 = nv0; v1 = nv1; v2 = nv2;
        }
        float a_s = sp[30]*a0 + sp[31]*a1 + sp[32]*a2;
        float b_s = sp[30]*v0 + sp[31]*v1 + sp[32]*v2 + bb[12];

        d_affine[c] = make_float4(a_s, b_s - 0.5f * a_s, gated ? 1.0f : 0.0f, b_s);
    }
}

// -------------------------------------------------------------------------
// Generic slow logits (gated fallback only). Loop-based, reads params from
// global each use -> tiny register footprint so it never taxes the fast path.
// -------------------------------------------------------------------------
__device__ __noinline__ float logits_slow(const float* __restrict__ P, float t)
{
    float h[3];
#pragma unroll 1
    for (int i = 0; i < 3; i++) {
        float g = fmaf(P[i], t, P[33 + i]);
        h[i] = g + P[46 + i] * tanhf(g);
    }
#pragma unroll 1
    for (int l = 1; l < 4; l++) {
        const float* M = P + 3 + (l - 1) * 9;
        float g[3];
#pragma unroll 1
        for (int r = 0; r < 3; r++) {
            float s = P[33 + 3 * l + r];
#pragma unroll 1
            for (int k = 0; k < 3; k++) s = fmaf(M[3 * r + k], h[k], s);
            g[r] = s + P[46 + 3 * l + r] * tanhf(s);
        }
        h[0] = g[0]; h[1] = g[1]; h[2] = g[2];
    }
    float o = P[33 + 12];
#pragma unroll 1
    for (int k = 0; k < 3; k++) o = fmaf(P[30 + k], h[k], o);
    return o + P[46 + 12] * tanhf(o);
}

__device__ __forceinline__ float lk_from_LU(float L, float U)
{
    float su = L + U;
    float s = (su > 0.0f) ? -1.0f : ((su < 0.0f) ? 1.0f : 0.0f);  // -sign(L+U)
    float lk = fabsf(fast_sigmoid(s * U) - fast_sigmoid(s * L));
    return fmaxf(lk, 1e-9f);
}

// -------------------------------------------------------------------------
// Hot kernel: pure streaming. 256 thr x 4 elems = 1024/block; 1024 | 9216
// so each block is channel-uniform. Fast path: L = fma(a,v,bm), U = L + a.
// -------------------------------------------------------------------------
__global__ void __launch_bounds__(256, 6) eb_main(
    const float4* __restrict__ x4, const float4* __restrict__ n4,
    float* __restrict__ out, int n4tot)
{
    int c = (int)((blockIdx.x * 1024u) / HW_) % CC;
    float4 A = d_affine[c];

    int i4 = blockIdx.x * 256 + threadIdx.x;
    float4 xv = __ldcs(x4 + i4);
    float4 nv = __ldcs(n4 + i4);
    float4 v = make_float4(xv.x + nv.x, xv.y + nv.y, xv.z + nv.z, xv.w + nv.w);

    float4* o4 = (float4*)out;
    __stcs(o4 + i4, v);  // outputs = v

    float4 lk;
    if (A.z == 0.0f) {
        float a = A.x, bm = A.y;
        float Lx = fmaf(a, v.x, bm), Ly = fmaf(a, v.y, bm);
        float Lz = fmaf(a, v.z, bm), Lw = fmaf(a, v.w, bm);
        lk.x = lk_from_LU(Lx, Lx + a);
        lk.y = lk_from_LU(Ly, Ly + a);
        lk.z = lk_from_LU(Lz, Lz + a);
        lk.w = lk_from_LU(Lw, Lw + a);
    } else {
        const float* P = d_param + c * PSTRIDE;
        lk.x = lk_from_LU(logits_slow(P, v.x - 0.5f), logits_slow(P, v.x + 0.5f));
        lk.y = lk_from_LU(logits_slow(P, v.y - 0.5f), logits_slow(P, v.y + 0.5f));
        lk.z = lk_from_LU(logits_slow(P, v.z - 0.5f), logits_slow(P, v.z + 0.5f));
        lk.w = lk_from_LU(logits_slow(P, v.w - 0.5f), logits_slow(P, v.w + 0.5f));
    }
    __stcs(o4 + n4tot + i4, lk);  // likelihood
}

extern "C" void kernel_launch(void* const* d_in, const int* in_sizes, int n_in,
                              void* d_out, int out_size)
{
    const float* X  = (const float*)d_in[0];
    const float* NZ = (const float*)d_in[1];

    const float *m[5], *b[5], *f[5];
    if (in_sizes[3] == 3 * in_sizes[2]) {      // signature order
        for (int i = 0; i < 5; i++) {
            m[i] = (const float*)d_in[2 + i];
            b[i] = (const float*)d_in[7 + i];
            f[i] = (const float*)d_in[12 + i];
        }
    } else {                                   // dict order m,b,f interleaved
        for (int i = 0; i < 5; i++) {
            m[i] = (const float*)d_in[2 + 3 * i];
            b[i] = (const float*)d_in[3 + 3 * i];
            f[i] = (const float*)d_in[4 + 3 * i];
        }
    }

    int N = in_sizes[0];  // B*C*H*W = 28,311,552

    eb_prep<<<24, 256>>>(
        m[0], m[1], m[2], m[3], m[4],
        b[0], b[1], b[2], b[3], b[4],
        f[0], f[1], f[2], f[3], f[4]);

    int blocks = N / 1024;  // 256 threads * 4 elems
    eb_main<<<blocks, 256>>>((const float4*)X, (const float4*)NZ,
                             (float*)d_out, N / 4);
}